// round 16
// baseline (speedup 1.0000x reference)
#include <cuda_runtime.h>
#include <cuda_fp16.h>

#define DIMC 128
#define HEADS 8
#define HD 16
#define HH 32
#define WW 32
#define ZZ 8
#define NPTS 8192   // 32*32*8
#define NXV 1024    // 16*16*4
#define LOG2E 1.44269504f

// Scratch (device globals)
__device__ float   g_stats_x[DIMC * 2];
__device__ float   g_stats_s[DIMC * 2];
__device__ __half2 g_q16[HEADS * NXV * 8];     // [head][m][8 half2]
__device__ __half2 g_k16[HEADS * NPTS * 8];    // [head][n][8 half2]
__device__ __half2 g_v16[HEADS * NPTS * 8];    // [head][n][8 half2]
__device__ __half  g_o16[NPTS * DIMC];         // [n][j] row-major attn output
__device__ __half  g_WkT[DIMC * DIMC];         // [j][c] fp16 transposed weights
__device__ __half  g_WvT[DIMC * DIMC];
__device__ __half  g_WqT[DIMC * DIMC];
__device__ __half  g_WoT[DIMC * DIMC];         // [c][j] fp16 (Wo transposed)

// Phase counters (self-resetting each pipeline run)
__device__ unsigned g_cnt_stats = 0;   // -> 320
__device__ unsigned g_cnt_attn  = 0;   // -> 256
__device__ unsigned g_cnt_done  = 0;   // -> 128

__device__ __forceinline__ float ex2(float x) {
    float r; asm("ex2.approx.ftz.f32 %0,%1;" : "=f"(r) : "f"(x)); return r;
}
__device__ __forceinline__ unsigned ldacq(const unsigned* p) {
    unsigned v; asm volatile("ld.acquire.gpu.u32 %0,[%1];" : "=r"(v) : "l"(p));
    return v;
}
__device__ __forceinline__ void phase_arrive(unsigned* cnt) {
    __threadfence();
    __syncthreads();
    if (threadIdx.x == 0) atomicAdd(cnt, 1u);
}
__device__ __forceinline__ void phase_wait(const unsigned* cnt, unsigned target) {
    if (threadIdx.x == 0) {
        while (ldacq(cnt) < target) __nanosleep(64);
    }
    __syncthreads();
}

// ---- mma.sync m16n8k16 fp16 -> fp32 ---------------------------------------
__device__ __forceinline__ void mma16816(float* d, unsigned a0, unsigned a1,
                                         unsigned a2, unsigned a3,
                                         unsigned b0, unsigned b1) {
    asm volatile(
        "mma.sync.aligned.m16n8k16.row.col.f32.f16.f16.f32 "
        "{%0,%1,%2,%3},{%4,%5,%6,%7},{%8,%9},{%0,%1,%2,%3};"
        : "+f"(d[0]), "+f"(d[1]), "+f"(d[2]), "+f"(d[3])
        : "r"(a0), "r"(a1), "r"(a2), "r"(a3), "r"(b0), "r"(b1));
}

#define SSTR 136   // smem row stride (halves)

// ===========================================================================
// Kernel A: blocks [0,256) stats, [256,320) weight transpose, [320,456) qkv.
// qkv blocks spin until all 320 prep blocks have arrived.
// ===========================================================================
__global__ __launch_bounds__(256) void fusedA(
        const float* __restrict__ x,  const float* __restrict__ skip,
        const float* __restrict__ Wq, const float* __restrict__ bq,
        const float* __restrict__ Wk, const float* __restrict__ bk,
        const float* __restrict__ Wv, const float* __restrict__ bv,
        const float* __restrict__ Wo) {
    extern __shared__ char dynsmem[];
    int b = blockIdx.x;
    int tid = threadIdx.x;

    if (b < 320) {
        if (b >= 256) {
            // ---- weight transpose to fp16 (64 blocks = 4 mats x 16 tiles) ----
            float (*ts)[33] = (float(*)[33])dynsmem;
            int t = b - 256;
            int m = t >> 4, tile = t & 15;
            int tr = (tile >> 2) * 32, tc = (tile & 3) * 32;
            const float* src = (m == 0) ? Wk : (m == 1) ? Wv : (m == 2) ? Wq : Wo;
            __half* dst = (m == 0) ? g_WkT : (m == 1) ? g_WvT : (m == 2) ? g_WqT : g_WoT;
            int lr = tid >> 5, lc = tid & 31;
            #pragma unroll
            for (int i = 0; i < 4; i++)
                ts[lr + i * 8][lc] = src[(tc + lr + i * 8) * DIMC + tr + lc];
            __syncthreads();
            #pragma unroll
            for (int i = 0; i < 4; i++)
                dst[(tr + lr + i * 8) * DIMC + tc + lc] = __float2half(ts[lc][lr + i * 8]);
        } else {
            // ---- instance-norm statistics ----
            float* sh1 = (float*)dynsmem;
            float* sh2 = sh1 + 8;
            int c = b;
            const float* src; int n; float* dst;
            if (c < DIMC) { src = x + c * NXV;              n = NXV;  dst = g_stats_x + c * 2; }
            else          { src = skip + (c - DIMC) * NPTS; n = NPTS; dst = g_stats_s + (c - DIMC) * 2; }
            float s = 0.f, s2 = 0.f;
            for (int i = tid; i < n; i += 256) {
                float v = src[i];
                s += v; s2 += v * v;
            }
            #pragma unroll
            for (int o = 16; o; o >>= 1) {
                s  += __shfl_down_sync(0xffffffffu, s,  o);
                s2 += __shfl_down_sync(0xffffffffu, s2, o);
            }
            int wid = tid >> 5, lid = tid & 31;
            if (lid == 0) { sh1[wid] = s; sh2[wid] = s2; }
            __syncthreads();
            if (tid == 0) {
                float ts2sum = 0.f, tss = 0.f;
                #pragma unroll
                for (int i = 0; i < 8; i++) { tss += sh1[i]; ts2sum += sh2[i]; }
                float mean = tss / n;
                float var  = ts2sum / n - mean * mean;
                dst[0] = mean;
                dst[1] = rsqrtf(var + 1e-5f);
            }
        }
        phase_arrive(&g_cnt_stats);
        return;
    }

    // ---- qkv projection via tensor cores ----
    __half (*sA)[SSTR] = (__half(*)[SSTR])dynsmem;              // [n 128][c 128]
    __half (*sB)[SSTR] = (__half(*)[SSTR])(dynsmem + 128 * SSTR * 2);

    int bid = b - 320;
    const float *src, *bt, *stats;
    const __half* WT;
    __half2* outp; int strideN; float scale; int n0;
    if (bid < 64) {
        src = skip; WT = g_WkT; bt = bk; stats = g_stats_s;
        outp = g_k16; strideN = NPTS; scale = 1.f; n0 = bid * 128;
    } else if (bid < 128) {
        src = skip; WT = g_WvT; bt = bv; stats = g_stats_s;
        outp = g_v16; strideN = NPTS; scale = 1.f; n0 = (bid - 64) * 128;
    } else {
        src = x; WT = g_WqT; bt = bq; stats = g_stats_x;
        outp = g_q16; strideN = NXV; scale = 0.25f * LOG2E; n0 = (bid - 128) * 128;
    }

    phase_wait(&g_cnt_stats, 320);

    // Stage A (normalize + transpose fp32 [c][n] -> fp16 [n][c])
    {
        int c = tid & 127, nh = (tid >> 7) * 64;
        float mu = stats[c * 2], rs = stats[c * 2 + 1];
        const float* sp = src + c * strideN + n0 + nh;
        #pragma unroll
        for (int i = 0; i < 16; i++) {
            float4 v = *(const float4*)(sp + i * 4);
            int n = nh + i * 4;
            sA[n + 0][c] = __float2half((v.x - mu) * rs);
            sA[n + 1][c] = __float2half((v.y - mu) * rs);
            sA[n + 2][c] = __float2half((v.z - mu) * rs);
            sA[n + 3][c] = __float2half((v.w - mu) * rs);
        }
    }
    // Stage B: vectorized fp16 copy of precomputed W^T [j][c]
    {
        int j = tid >> 1, hf = tid & 1;
        const float4* wp = (const float4*)(WT + j * DIMC + hf * 64);
        float4* dp = (float4*)&sB[j][hf * 64];
        #pragma unroll
        for (int i = 0; i < 8; i++) dp[i] = wp[i];
    }
    __syncthreads();

    int w = tid >> 5, t = tid & 31;
    int g = t >> 2, i2 = (t & 3) * 2;
    int mrow = w * 16;

    float acc[16][4];
    #pragma unroll
    for (int nt = 0; nt < 16; nt++)
        #pragma unroll
        for (int p = 0; p < 4; p++) acc[nt][p] = 0.f;

    #pragma unroll
    for (int kc = 0; kc < 8; kc++) {
        int k0 = kc * 16;
        unsigned a0 = *(const unsigned*)&sA[mrow + g][k0 + i2];
        unsigned a1 = *(const unsigned*)&sA[mrow + g + 8][k0 + i2];
        unsigned a2 = *(const unsigned*)&sA[mrow + g][k0 + i2 + 8];
        unsigned a3 = *(const unsigned*)&sA[mrow + g + 8][k0 + i2 + 8];
        #pragma unroll
        for (int nt = 0; nt < 16; nt++) {
            unsigned b0 = *(const unsigned*)&sB[nt * 8 + g][k0 + i2];
            unsigned b1 = *(const unsigned*)&sB[nt * 8 + g][k0 + i2 + 8];
            mma16816(acc[nt], a0, a1, a2, a3, b0, b1);
        }
    }

    int n1 = n0 + mrow + g;
    #pragma unroll
    for (int nt = 0; nt < 16; nt++) {
        int j = nt * 8 + i2;
        float2 bb = *(const float2*)&bt[j];
        int head = j >> 4;
        int jj = (j & 15) >> 1;
        outp[(head * strideN + n1) * 8 + jj] =
            __floats2half2_rn((acc[nt][0] + bb.x) * scale,
                              (acc[nt][1] + bb.y) * scale);
        outp[(head * strideN + n1 + 8) * 8 + jj] =
            __floats2half2_rn((acc[nt][2] + bb.x) * scale,
                              (acc[nt][3] + bb.y) * scale);
    }
}

// ===========================================================================
// Kernel B: blocks [0,256) attention (4h x 8w x 8z tile, 256 thr, proven
// R3/R13 inner loop with ex2), blocks [256,384) output projection (spins
// until all attn blocks arrive). Last proj block resets counters.
// ===========================================================================
#define WH 12   // w halo extent
__global__ __launch_bounds__(256) void fusedB(
        const float* __restrict__ rpb, const float* __restrict__ bo,
        float* __restrict__ outp) {
    extern __shared__ char dynsmem[];
    int b = blockIdx.x;
    int tid = threadIdx.x;

    if (b < 256) {
        // ---- attention ----
        float4* sk4 = (float4*)dynsmem;           // 1536 float4 (768 pos * 2)
        float4* sv4 = sk4 + 1536;                 // 1536 float4
        float*  sb  = (float*)(sv4 + 1536);       // 729 bias

        int head = b >> 5;
        int h0 = (b & 7) * 4, w0 = ((b >> 3) & 3) * 8;
        int hlo = min(max(h0 - 2, 0), HH - 5);
        int wlo = min(max(w0 - 2, 0), WW - 5);

        for (int i = tid; i < 729; i += 256) sb[i] = rpb[head * 729 + i] * LOG2E;

        const float4* gk4 = (const float4*)g_k16 + head * (NPTS * 2);
        const float4* gv4 = (const float4*)g_v16 + head * (NPTS * 2);
        #pragma unroll
        for (int it = 0; it < 6; it++) {
            int idx = it * 256 + tid;             // 1536 (pos,d4) pairs
            int d4 = idx & 1, pos = idx >> 1;
            int col = pos >> 3, z1 = pos & 7;
            int wh = col / WH, wwi = col - wh * WH;
            int gh = min(hlo + wh, HH - 1);
            int gw = min(wlo + wwi, WW - 1);
            int n = gh * 256 + gw * 8 + z1;
            int s = pos * 2 + (d4 ^ (col & 1));   // XOR swizzle
            sk4[s] = gk4[n * 2 + d4];
            sv4[s] = gv4[n * 2 + d4];
        }
        __syncthreads();

        int z = tid & 7, dw = (tid >> 3) & 7, dh = tid >> 6;
        int h = h0 + dh, w = w0 + dw;
        int sh = min(max(h - 2, 0), HH - 5);
        int sw = min(max(w - 2, 0), WW - 5);
        int sz = min(max(z - 2, 0), ZZ - 5);
        int m = (h >> 1) * 64 + (w >> 1) * 4 + (z >> 1);

        __half2 q2[8];
        {
            const float4* gq4 = (const float4*)g_q16 + (head * NXV + m) * 2;
            float4 qA = gq4[0], qB = gq4[1];
            const __half2* qa = (const __half2*)&qA;
            const __half2* qb = (const __half2*)&qB;
            #pragma unroll
            for (int i = 0; i < 4; i++) { q2[i] = qa[i]; q2[4 + i] = qb[i]; }
        }

        int bh = sh - h + 4, bw = sw - w + 4, bz = sz - z + 4;

        float sum = 0.f;
        float acc[16];
        #pragma unroll
        for (int d = 0; d < 16; d++) acc[d] = 0.f;

        for (int jh = 0; jh < 5; jh++) {
            int colh = (sh + jh - hlo) * WH;
            const float* bph = sb + (bh + jh) * 81 + bz;
            for (int jw = 0; jw < 5; jw++) {
                int col = colh + (sw + jw - wlo);
                int e = col & 1;
                const float4* kp = sk4 + col * 16 + sz * 2;
                const float4* vp = sv4 + col * 16 + sz * 2;
                const float* bp = bph + (bw + jw) * 9;
                #pragma unroll
                for (int jz = 0; jz < 5; jz++) {
                    float4 kA = kp[jz * 2 + e];
                    float4 kB = kp[jz * 2 + 1 - e];
                    const __half2* ka = (const __half2*)&kA;
                    const __half2* kb = (const __half2*)&kB;
                    __half2 s0 = __hmul2(q2[0], ka[0]);
                    __half2 s1 = __hmul2(q2[1], ka[1]);
                    s0 = __hfma2(q2[2], ka[2], s0);
                    s1 = __hfma2(q2[3], ka[3], s1);
                    s0 = __hfma2(q2[4], kb[0], s0);
                    s1 = __hfma2(q2[5], kb[1], s1);
                    s0 = __hfma2(q2[6], kb[2], s0);
                    s1 = __hfma2(q2[7], kb[3], s1);
                    float2 lf = __half22float2(__hadd2(s0, s1));
                    float l = bp[jz] + lf.x + lf.y;
                    float p = ex2(l);
                    sum += p;
                    float4 vA = vp[jz * 2 + e];
                    float4 vB = vp[jz * 2 + 1 - e];
                    const __half2* va = (const __half2*)&vA;
                    const __half2* vb = (const __half2*)&vB;
                    #pragma unroll
                    for (int i = 0; i < 4; i++) {
                        float2 f0 = __half22float2(va[i]);
                        float2 f1 = __half22float2(vb[i]);
                        acc[2 * i]         += p * f0.x;
                        acc[2 * i + 1]     += p * f0.y;
                        acc[8 + 2 * i]     += p * f1.x;
                        acc[8 + 2 * i + 1] += p * f1.y;
                    }
                }
            }
        }

        float inv = 1.f / sum;
        int n = h * 256 + w * 8 + z;
        __half2 o2[8];
        #pragma unroll
        for (int d = 0; d < 8; d++)
            o2[d] = __floats2half2_rn(acc[2 * d] * inv, acc[2 * d + 1] * inv);
        float4* dst = (float4*)(g_o16 + n * DIMC + head * 16);
        dst[0] = ((const float4*)o2)[0];
        dst[1] = ((const float4*)o2)[1];

        phase_arrive(&g_cnt_attn);
        return;
    }

    // ---- output projection ----
    __half (*sA)[SSTR] = (__half(*)[SSTR])dynsmem;                  // [n 128][j 128]
    __half (*sB)[SSTR] = (__half(*)[SSTR])(dynsmem + 128 * SSTR * 2); // [c 64][j 128]

    int bid = b - 256;
    int n0 = (bid >> 1) * 128;
    int c0 = (bid & 1) * 64;

    // Stage B first (independent of attn): copy fp16 [c][j] from WoT
    {
        int r = tid >> 2, qt = (tid & 3) * 32;
        const float4* wp = (const float4*)(g_WoT + (c0 + r) * DIMC + qt);
        float4* dp = (float4*)&sB[r][qt];
        #pragma unroll
        for (int i = 0; i < 4; i++) dp[i] = wp[i];
    }

    phase_wait(&g_cnt_attn, 256);

    // Stage A: copy fp16 [n][j]
    {
        int n = tid & 127, jh = (tid >> 7) * 64;
        const float4* gA = (const float4*)(g_o16 + (n0 + n) * DIMC + jh);
        float4* dA = (float4*)&sA[n][jh];
        #pragma unroll
        for (int i = 0; i < 8; i++) dA[i] = gA[i];
    }
    __syncthreads();

    int w = tid >> 5, t = tid & 31;
    int g = t >> 2, i2 = (t & 3) * 2;
    int mrow = w * 16;

    float acc[8][4];
    #pragma unroll
    for (int nt = 0; nt < 8; nt++)
        #pragma unroll
        for (int p = 0; p < 4; p++) acc[nt][p] = 0.f;

    #pragma unroll
    for (int kc = 0; kc < 8; kc++) {
        int k0 = kc * 16;
        unsigned a0 = *(const unsigned*)&sA[mrow + g][k0 + i2];
        unsigned a1 = *(const unsigned*)&sA[mrow + g + 8][k0 + i2];
        unsigned a2 = *(const unsigned*)&sA[mrow + g][k0 + i2 + 8];
        unsigned a3 = *(const unsigned*)&sA[mrow + g + 8][k0 + i2 + 8];
        #pragma unroll
        for (int nt = 0; nt < 8; nt++) {
            unsigned b0 = *(const unsigned*)&sB[nt * 8 + g][k0 + i2];
            unsigned b1 = *(const unsigned*)&sB[nt * 8 + g][k0 + i2 + 8];
            mma16816(acc[nt], a0, a1, a2, a3, b0, b1);
        }
    }

    // Epilogue: out[c][n] fp32 + bias
    int n1 = n0 + mrow + g;
    #pragma unroll
    for (int nt = 0; nt < 8; nt++) {
        int c = c0 + nt * 8 + i2;
        float2 bb = *(const float2*)&bo[c];
        outp[c * NPTS + n1]           = acc[nt][0] + bb.x;
        outp[(c + 1) * NPTS + n1]     = acc[nt][1] + bb.y;
        outp[c * NPTS + n1 + 8]       = acc[nt][2] + bb.x;
        outp[(c + 1) * NPTS + n1 + 8] = acc[nt][3] + bb.y;
    }

    // Completion: last proj block resets all counters for the next replay.
    __threadfence();
    __syncthreads();
    if (tid == 0) {
        unsigned t2 = atomicAdd(&g_cnt_done, 1u);
        if (t2 == 127u) {
            g_cnt_stats = 0u;
            g_cnt_attn  = 0u;
            g_cnt_done  = 0u;
            __threadfence();
        }
    }
}

// ---------------------------------------------------------------------------
extern "C" void kernel_launch(void* const* d_in, const int* in_sizes, int n_in,
                              void* d_out, int out_size) {
    const float* x    = (const float*)d_in[0];
    const float* skip = (const float*)d_in[1];
    const float* Wq   = (const float*)d_in[2];
    const float* bq   = (const float*)d_in[3];
    const float* Wk   = (const float*)d_in[4];
    const float* bk   = (const float*)d_in[5];
    const float* Wv   = (const float*)d_in[6];
    const float* bv   = (const float*)d_in[7];
    const float* rpb  = (const float*)d_in[8];
    const float* Wo   = (const float*)d_in[9];
    const float* bo   = (const float*)d_in[10];
    float* outp = (float*)d_out;

    const int smemA = 256 * SSTR * sizeof(__half);            // ~69.6KB (qkv)
    const int smemB = 192 * SSTR * sizeof(__half);            // ~52.3KB (attn/proj)
    cudaFuncSetAttribute(fusedA, cudaFuncAttributeMaxDynamicSharedMemorySize, smemA);
    cudaFuncSetAttribute(fusedB, cudaFuncAttributeMaxDynamicSharedMemorySize, smemB);

    fusedA<<<456, 256, smemA>>>(x, skip, Wq, bq, Wk, bk, Wv, bv, Wo);
    fusedB<<<384, 256, smemB>>>(rpb, bo, outp);
}